// round 11
// baseline (speedup 1.0000x reference)
#include <cuda_runtime.h>
#include <cuda_fp16.h>
#include <cstdint>

// ---------------------------------------------------------------- constants
#define H 128
#define BB 256
#define SS 1024
#define ROWS (BB*(SS-1))          // 261888
#define TM 128                    // rows per tile
#define NTILES (ROWS/TM)          // 2046 (exact)
#define NCTA 296                  // persistent CTAs (2 per SM x 148)

#define YSTRB 144                 // bytes per int8 y-tile row (16B-aligned pad)
#define YTILE (128*YSTRB)         // 18432 bytes

// quantization scales (powers of two; exact rescale)
#define SCALE_Y 16.0f
#define SCALE_D 2048.0f
#define INV_SCALE (1.0f/32768.0f)

// dynamic smem layout (bytes)
#define SM_DF   0                         // D int8 B-frags, 16384
#define SM_Y0   16384                     // int8 y buf0, 18432
#define SM_Y1   (SM_Y0 + YTILE)
#define SMEM_TOTAL (SM_Y1 + YTILE)        // 53248 -> 2 CTAs/SM (reg-capped)

// ---------------------------------------------------------------- scratch
__device__ float          g_B[H*H];          // C^2
__device__ signed char    g_Dfrag[H*H];      // D int8, m16n8k32 B-frag order
__device__ double         g_partials[NCTA];
__device__ double         g_l2row[H];
__device__ double         g_l2;
__device__ unsigned int   g_done;
__device__ unsigned int   g_bar1;
__device__ unsigned int   g_bar2;

// ---------------------------------------------------------------- helpers
__device__ __forceinline__ uint32_t smem_u32(const void* p) {
    uint32_t a;
    asm("{ .reg .u64 t; cvta.to.shared.u64 t, %1; cvt.u32.u64 %0, t; }"
        : "=r"(a) : "l"(p));
    return a;
}

#define MMA_S8(ACC, A0, A1, A2, A3, B0, B1)                                 \
    asm volatile(                                                           \
        "mma.sync.aligned.m16n8k32.row.col.s32.s8.s8.s32 "                  \
        "{%0,%1,%2,%3}, {%4,%5,%6,%7}, {%8,%9}, {%0,%1,%2,%3};"             \
        : "+r"((ACC)[0]), "+r"((ACC)[1]), "+r"((ACC)[2]), "+r"((ACC)[3])    \
        : "r"(A0), "r"(A1), "r"(A2), "r"(A3), "r"(B0), "r"(B1))

__device__ __forceinline__ int q8(float f, float scale) {
    float v = fminf(fmaxf(f * scale, -127.f), 127.f);
    return __float2int_rn(v);
}
__device__ __forceinline__ uint32_t pack4(int a, int b, int c, int d) {
    return (uint32_t)(a & 0xff) | ((uint32_t)(b & 0xff) << 8) |
           ((uint32_t)(c & 0xff) << 16) | ((uint32_t)d << 24);
}

// ---------------------------------------------------------------- fused prep
// grid = 128 blocks x 512 threads, co-resident -> software global barrier.
__global__ void __launch_bounds__(512) prep_kernel(const float* __restrict__ coeff) {
    __shared__ float crow[H];
    __shared__ float brow[H];
    __shared__ float c2row[H];
    __shared__ float part[4][H];
    const int i  = blockIdx.x;
    const int t  = threadIdx.x;
    const int j  = t & 127;
    const int kq = t >> 7;

    if (t < H) crow[t] = coeff[i*H + t];
    __syncthreads();

    {   // phase 1 partial: sum over k-quarter of crow[k]*C[k][j]
        float a0 = 0.f, a1 = 0.f;
        int k0 = kq * 32;
        #pragma unroll
        for (int k = 0; k < 32; k += 2) {
            a0 = fmaf(crow[k0+k],   __ldg(coeff + (k0+k)*H + j),   a0);
            a1 = fmaf(crow[k0+k+1], __ldg(coeff + (k0+k+1)*H + j), a1);
        }
        part[kq][j] = a0 + a1;
    }
    __syncthreads();
    if (t < H) {
        float b = (part[0][t] + part[1][t]) + (part[2][t] + part[3][t]);
        g_B[i*H + t] = b;
        brow[t]  = b;
        c2row[t] = crow[t] * (1.0f/6.0f) + b * (1.0f/24.0f);
        float c = crow[t];
        float cc = c * c;
        float v = cc * cc;
        #pragma unroll
        for (int off = 16; off; off >>= 1)
            v += __shfl_down_sync(0xffffffffu, v, off);
        __shared__ float lred[4];
        if ((t & 31) == 0) lred[t >> 5] = v;
        __syncthreads();
        if (t == 0)
            g_l2row[i] = (double)((lred[0] + lred[1]) + (lred[2] + lred[3]));
    }

    // global barrier (128 blocks, all resident)
    __threadfence();
    __syncthreads();
    if (t == 0) {
        atomicAdd(&g_bar1, 1u);
        while (*(volatile unsigned int*)&g_bar1 < (unsigned int)H) { }
    }
    __syncthreads();
    __threadfence();

    {   // phase 2 partial: sum over k-quarter of c2row[k]*B[k][j]
        float a0 = 0.f, a1 = 0.f;
        int k0 = kq * 32;
        #pragma unroll
        for (int k = 0; k < 32; k += 2) {
            a0 = fmaf(c2row[k0+k],   __ldg(g_B + (k0+k)*H + j),   a0);
            a1 = fmaf(c2row[k0+k+1], __ldg(g_B + (k0+k+1)*H + j), a1);
        }
        part[kq][j] = a0 + a1;
    }
    __syncthreads();
    if (t < H) {
        float d = crow[t] + 0.5f * brow[t]
                + ((part[0][t] + part[1][t]) + (part[2][t] + part[3][t]));
        // scatter int8 to mma m16n8k32 B-frag order (i = n, t = k)
        int ks = t >> 5, kin = t & 31;
        int reg = kin >> 4, kl = kin & 15;
        int lane = ((i & 7) << 2) + (kl >> 2);
        int byte = kl & 3;
        int ntile = i >> 3;
        int off = ((((ks*16 + ntile)*32 + lane)*2 + reg) << 2) + byte;
        g_Dfrag[off] = (signed char)q8(d, SCALE_D);
    }
    if (i == 0 && t == 0) {
        double s = 0.0;
        #pragma unroll
        for (int r = 0; r < H; r++) s += g_l2row[r];
        g_l2 = s;
        g_done = 0u;
    }

    __threadfence();
    __syncthreads();
    if (t == 0) {
        unsigned int old = atomicAdd(&g_bar2, 1u);
        if (old == (unsigned int)(H - 1)) { g_bar1 = 0u; g_bar2 = 0u; }
    }
}

// ---------------------------------------------------------------- convert
// load fp32 y rows of tile tt -> int8 (x SCALE_Y) smem buffer, stride 144B
__device__ __forceinline__ void convert_tile(const float* __restrict__ x,
                                             char* __restrict__ ybuf,
                                             int tt, int tid) {
    int row = tid >> 1, half = tid & 1;
    int rg = tt*TM + row;
    int b  = rg / 1023;
    int s  = rg - b*1023;
    const float4* src = (const float4*)(x + (size_t)(b*SS + s)*H) + half*16;
    char* dst = ybuf + (size_t)row*YSTRB + half*64;
    #pragma unroll
    for (int q = 0; q < 4; q++) {
        float4 v0 = src[4*q+0], v1 = src[4*q+1];
        float4 v2 = src[4*q+2], v3 = src[4*q+3];
        uint4 u;
        u.x = pack4(q8(v0.x,SCALE_Y), q8(v0.y,SCALE_Y), q8(v0.z,SCALE_Y), q8(v0.w,SCALE_Y));
        u.y = pack4(q8(v1.x,SCALE_Y), q8(v1.y,SCALE_Y), q8(v1.z,SCALE_Y), q8(v1.w,SCALE_Y));
        u.z = pack4(q8(v2.x,SCALE_Y), q8(v2.y,SCALE_Y), q8(v2.z,SCALE_Y), q8(v2.w,SCALE_Y));
        u.w = pack4(q8(v3.x,SCALE_Y), q8(v3.y,SCALE_Y), q8(v3.z,SCALE_Y), q8(v3.w,SCALE_Y));
        *(uint4*)(dst + q*16) = u;
    }
}

// ---------------------------------------------------------------- main
// Persistent: 296 CTAs x 256 threads, 2 CTAs/SM. D int8 staged once per CTA.
// Double-buffered int8 y tiles; int8 mma; epilogue y/x1 from global fp32.
__global__ void __launch_bounds__(256, 2)
main_kernel(const float* __restrict__ x, float* __restrict__ out) {
    extern __shared__ char smem[];
    const int tid  = threadIdx.x;
    const int w    = tid >> 5;
    const int lane = tid & 31;
    const int rb   = (w & 3) * 32;       // row base (2 m16 tiles)
    const int cb   = (w >> 2) * 8;       // n-tile base (8 tiles = 64 cols)

    // ---- stage D B-fragments once, 16KB
    {
        const uint4* df = (const uint4*)g_Dfrag;
        uint4* sh = (uint4*)(smem + SM_DF);
        #pragma unroll
        for (int i = 0; i < 4; i++) sh[tid + i*256] = df[tid + i*256];
    }

    int buf = 0;
    convert_tile(x, smem + SM_Y0, blockIdx.x, tid);
    __syncthreads();

    double csum = 0.0;

    for (int tile = blockIdx.x; tile < NTILES; tile += NCTA) {
        char* ycur = smem + (buf ? SM_Y1 : SM_Y0);
        char* ynxt = smem + (buf ? SM_Y0 : SM_Y1);

        // ---- int8 MMA mainloop
        int acc[2][8][4];
        #pragma unroll
        for (int rt = 0; rt < 2; rt++)
            #pragma unroll
            for (int t = 0; t < 8; t++) {
                acc[rt][t][0] = 0; acc[rt][t][1] = 0;
                acc[rt][t][2] = 0; acc[rt][t][3] = 0;
            }
        const uint32_t abase = smem_u32(ycur)
            + (uint32_t)((rb + (lane & 15))*YSTRB + (lane >> 4)*16);

        #pragma unroll
        for (int ks = 0; ks < 4; ks++) {
            uint2 bf[8];
            #pragma unroll
            for (int t = 0; t < 8; t++) {
                uint32_t foff = (uint32_t)(((ks*16 + cb + t)*32 + lane) * 8);
                bf[t] = *(const uint2*)(smem + SM_DF + foff);
            }
            #pragma unroll
            for (int rt = 0; rt < 2; rt++) {
                uint32_t a0, a1, a2, a3;
                asm volatile("ldmatrix.sync.aligned.m8n8.x4.shared.b16 {%0,%1,%2,%3}, [%4];"
                             : "=r"(a0), "=r"(a1), "=r"(a2), "=r"(a3)
                             : "r"(abase + (uint32_t)(rt*16*YSTRB) + ks*32));
                #pragma unroll
                for (int t = 0; t < 8; t++)
                    MMA_S8(acc[rt][t], a0, a1, a2, a3, bf[t].x, bf[t].y);
            }
        }

        // ---- prefetch/convert next tile into the other buffer
        int ntile = tile + NCTA;
        if (ntile < NTILES) convert_tile(x, ynxt, ntile, tid);

        // ---- epilogue: d = y + P - x1 ; y/x1 fp32 from global (L2-hot)
        float lsum = 0.f;
        #pragma unroll
        for (int rt = 0; rt < 2; rt++) {
            #pragma unroll
            for (int rr = 0; rr < 2; rr++) {
                int r = rb + rt*16 + rr*8 + (lane >> 2);
                int rg = tile*TM + r;
                int b  = rg / 1023;
                int s  = rg - b*1023;
                const float* base = x + (size_t)(b*SS + s)*H;
                #pragma unroll
                for (int t = 0; t < 8; t++) {
                    int col = (cb + t)*8 + (lane & 3)*2;
                    float2 yv = *(const float2*)(base + col);
                    float2 xv = *(const float2*)(base + H + col);   // row s+1
                    float p0 = (float)acc[rt][t][rr*2+0] * INV_SCALE;
                    float p1 = (float)acc[rt][t][rr*2+1] * INV_SCALE;
                    float d;
                    d = yv.x + p0 - xv.x; lsum = fmaf(d, d, lsum);
                    d = yv.y + p1 - xv.y; lsum = fmaf(d, d, lsum);
                }
            }
        }

        // ---- CTA reduction for this tile
        #pragma unroll
        for (int off = 16; off; off >>= 1)
            lsum += __shfl_down_sync(0xffffffffu, lsum, off);
        __shared__ float red[8];
        if (lane == 0) red[w] = lsum;
        __syncthreads();
        if (tid == 0) {
            float s = 0.f;
            #pragma unroll
            for (int i = 0; i < 8; i++) s += red[i];
            csum += (double)s;
        }
        __syncthreads();
        buf ^= 1;
    }

    // ---- publish per-CTA partial; last CTA folds (fixed order)
    __shared__ bool is_last;
    if (tid == 0) {
        g_partials[blockIdx.x] = csum;
        __threadfence();
        unsigned int old = atomicAdd(&g_done, 1u);
        is_last = (old == (unsigned int)(NCTA - 1));
    }
    __syncthreads();

    if (is_last) {
        double s = (tid < NCTA) ? g_partials[tid] : 0.0;
        if (tid + 256 < NCTA) s += g_partials[tid + 256];
        __shared__ double sd[256];
        sd[tid] = s; __syncthreads();
        for (int off = 128; off; off >>= 1) {
            if (tid < off) sd[tid] += sd[tid + off];
            __syncthreads();
        }
        if (tid == 0) {
            double step_loss = sd[0] / ((double)ROWS * (double)H);
            double l2_loss   = g_l2 / ((double)H * (double)H);
            out[0] = (float)(step_loss + 0.001 * l2_loss);
        }
    }
}

// ---------------------------------------------------------------- launch
extern "C" void kernel_launch(void* const* d_in, const int* in_sizes, int n_in,
                              void* d_out, int out_size) {
    const float* x     = (const float*)d_in[0];
    const float* coeff = (const float*)d_in[1];
    if (n_in >= 2 && in_sizes[0] == H*H) {
        coeff = (const float*)d_in[0];
        x     = (const float*)d_in[1];
    }
    float* out = (float*)d_out;

    cudaFuncSetAttribute(main_kernel,
                         cudaFuncAttributeMaxDynamicSharedMemorySize, SMEM_TOTAL);

    prep_kernel<<<H, 512>>>(coeff);
    main_kernel<<<NCTA, 256, SMEM_TOTAL>>>(x, out);
}

// round 12
// speedup vs baseline: 1.9190x; 1.9190x over previous
#include <cuda_runtime.h>
#include <cuda_fp16.h>
#include <cstdint>

// ---------------------------------------------------------------- constants
#define H 128
#define BB 256
#define SS 1024
#define ROWS (BB*(SS-1))          // 261888
#define TM 128                    // rows per tile
#define NTILES (ROWS/TM)          // 2046 (exact)
#define NCTA 296                  // persistent CTAs (2 per SM x 148)

#define YSTR 136                  // fp16 elems per y-tile row (272 B, padded)
#define YROWB (YSTR*2)            // 272
#define YTILE (129*YROWB)         // 35088 bytes (129 rows: +1 for x1 of row 127)

// dynamic smem layout (bytes)
#define SM_DF   0                         // D fp16 B-frags (paired), 32768
#define SM_Y0   32768
#define SM_Y1   (SM_Y0 + YTILE)
#define SMEM_TOTAL (SM_Y1 + YTILE)        // 102944 -> 2 CTAs/SM

// ---------------------------------------------------------------- scratch
__device__ float          g_B[H*H];          // C^2
__device__ __half         g_Dfrag[H*H];      // D fp16, paired B-frag order
__device__ double         g_partials[NCTA];
__device__ double         g_l2row[H];
__device__ double         g_l2;
__device__ unsigned int   g_done;
__device__ unsigned int   g_bar1;
__device__ unsigned int   g_bar2;

// ---------------------------------------------------------------- helpers
__device__ __forceinline__ uint32_t smem_u32(const void* p) {
    uint32_t a;
    asm("{ .reg .u64 t; cvta.to.shared.u64 t, %1; cvt.u32.u64 %0, t; }"
        : "=r"(a) : "l"(p));
    return a;
}

#define MMA_F16(ACC, A0, A1, A2, A3, B0, B1)                                \
    asm volatile(                                                           \
        "mma.sync.aligned.m16n8k16.row.col.f32.f16.f16.f32 "                \
        "{%0,%1,%2,%3}, {%4,%5,%6,%7}, {%8,%9}, {%0,%1,%2,%3};"             \
        : "+f"((ACC)[0]), "+f"((ACC)[1]), "+f"((ACC)[2]), "+f"((ACC)[3])    \
        : "r"(A0), "r"(A1), "r"(A2), "r"(A3), "r"(B0), "r"(B1))

// ---------------------------------------------------------------- fused prep
// grid = 128 blocks x 512 threads, co-resident -> software global barrier.
__global__ void __launch_bounds__(512) prep_kernel(const float* __restrict__ coeff) {
    __shared__ float crow[H];
    __shared__ float brow[H];
    __shared__ float c2row[H];
    __shared__ float part[4][H];
    const int i  = blockIdx.x;
    const int t  = threadIdx.x;
    const int j  = t & 127;
    const int kq = t >> 7;

    if (t < H) crow[t] = coeff[i*H + t];
    __syncthreads();

    {   // phase 1 partial: sum over k-quarter of crow[k]*C[k][j]
        float a0 = 0.f, a1 = 0.f;
        int k0 = kq * 32;
        #pragma unroll
        for (int k = 0; k < 32; k += 2) {
            a0 = fmaf(crow[k0+k],   __ldg(coeff + (k0+k)*H + j),   a0);
            a1 = fmaf(crow[k0+k+1], __ldg(coeff + (k0+k+1)*H + j), a1);
        }
        part[kq][j] = a0 + a1;
    }
    __syncthreads();
    if (t < H) {
        float b = (part[0][t] + part[1][t]) + (part[2][t] + part[3][t]);
        g_B[i*H + t] = b;
        brow[t]  = b;
        c2row[t] = crow[t] * (1.0f/6.0f) + b * (1.0f/24.0f);
        float c = crow[t];
        float cc = c * c;
        float v = cc * cc;
        #pragma unroll
        for (int off = 16; off; off >>= 1)
            v += __shfl_down_sync(0xffffffffu, v, off);
        __shared__ float lred[4];
        if ((t & 31) == 0) lred[t >> 5] = v;
        __syncthreads();
        if (t == 0)
            g_l2row[i] = (double)((lred[0] + lred[1]) + (lred[2] + lred[3]));
    }

    // global barrier (128 blocks, all resident)
    __threadfence();
    __syncthreads();
    if (t == 0) {
        atomicAdd(&g_bar1, 1u);
        while (*(volatile unsigned int*)&g_bar1 < (unsigned int)H) { }
    }
    __syncthreads();
    __threadfence();

    {   // phase 2 partial: sum over k-quarter of c2row[k]*B[k][j]
        float a0 = 0.f, a1 = 0.f;
        int k0 = kq * 32;
        #pragma unroll
        for (int k = 0; k < 32; k += 2) {
            a0 = fmaf(c2row[k0+k],   __ldg(g_B + (k0+k)*H + j),   a0);
            a1 = fmaf(c2row[k0+k+1], __ldg(g_B + (k0+k+1)*H + j), a1);
        }
        part[kq][j] = a0 + a1;
    }
    __syncthreads();
    if (t < H) {
        float d = crow[t] + 0.5f * brow[t]
                + ((part[0][t] + part[1][t]) + (part[2][t] + part[3][t]));
        // scatter fp16 to PAIRED m16n8k16 B-frag order (i = n, t = k):
        //   lane = ((n&7)<<2) + ((k&7)>>1), reg = (k&15)>>3, elem = k&1
        //   halves idx = ((ks*8 + n>>4)*32 + lane)*8 + ((n>>3)&1)*4 + reg*2 + elem
        int ks = t >> 4, kin = t & 15;
        int reg = kin >> 3;
        int lane = ((i & 7) << 2) + ((kin & 7) >> 1);
        int fidx = (((ks*8 + (i >> 4))*32 + lane) << 3)
                 + (((i >> 3) & 1) << 2) + (reg << 1) + (t & 1);
        g_Dfrag[fidx] = __float2half_rn(d);
    }
    if (i == 0 && t == 0) {
        double s = 0.0;
        #pragma unroll
        for (int r = 0; r < H; r++) s += g_l2row[r];
        g_l2 = s;
        g_done = 0u;
    }

    __threadfence();
    __syncthreads();
    if (t == 0) {
        unsigned int old = atomicAdd(&g_bar2, 1u);
        if (old == (unsigned int)(H - 1)) { g_bar1 = 0u; g_bar2 = 0u; }
    }
}

// ---------------------------------------------------------------- convert
// one half-row (64 floats) fp32 -> fp16
__device__ __forceinline__ void convert_halfrow(const float* __restrict__ src,
                                                char* __restrict__ dst) {
    const float4* s4 = (const float4*)src;
    #pragma unroll
    for (int q = 0; q < 8; q++) {
        float4 v0 = s4[2*q], v1 = s4[2*q + 1];
        __half2 p0 = __floats2half2_rn(v0.x, v0.y);
        __half2 p1 = __floats2half2_rn(v0.z, v0.w);
        __half2 p2 = __floats2half2_rn(v1.x, v1.y);
        __half2 p3 = __floats2half2_rn(v1.z, v1.w);
        uint4 u;
        u.x = *(uint32_t*)&p0; u.y = *(uint32_t*)&p1;
        u.z = *(uint32_t*)&p2; u.w = *(uint32_t*)&p3;
        *(uint4*)(dst + q*16) = u;
    }
}

// load 129 rows of tile tt into fp16 smem (row 128 = x1 of row 127)
__device__ __forceinline__ void convert_tile(const float* __restrict__ x,
                                             char* __restrict__ ybuf,
                                             int tt, int tid) {
    int row = tid >> 1, half = tid & 1;
    {
        int rg = tt*TM + row;
        int b  = rg / 1023;
        int s  = rg - b*1023;
        convert_halfrow(x + (size_t)(b*SS + s)*H + half*64,
                        ybuf + (size_t)row*YROWB + half*128);
    }
    if (tid < 2) {   // row 128: x1 of row 127 (always a valid x element)
        int rg = tt*TM + 127;
        int b  = rg / 1023;
        int s  = rg - b*1023;
        convert_halfrow(x + (size_t)(b*SS + s + 1)*H + half*64,
                        ybuf + (size_t)128*YROWB + half*128);
    }
}

// ---------------------------------------------------------------- main
// Persistent: 296 CTAs x 256 threads, 2 CTAs/SM. D staged once per CTA.
// Double-buffered 129-row fp16 y tiles; HMMA; epilogue all-smem (pred. fallback).
__global__ void __launch_bounds__(256, 2)
main_kernel(const float* __restrict__ x, float* __restrict__ out) {
    extern __shared__ char smem[];
    const int tid  = threadIdx.x;
    const int w    = tid >> 5;
    const int lane = tid & 31;
    const int rb   = (w & 3) * 32;       // row base (2 m16 tiles)
    const int cb   = (w >> 2) * 8;       // n-tile base (8 tiles = 64 cols)
    const int pb   = cb >> 1;            // n-pair base (4 pairs)

    // ---- stage D B-fragments once, 32KB
    {
        const uint4* df = (const uint4*)g_Dfrag;
        uint4* sh = (uint4*)(smem + SM_DF);
        #pragma unroll
        for (int i = 0; i < 8; i++) sh[tid + i*256] = df[tid + i*256];
    }

    int buf = 0;
    convert_tile(x, smem + SM_Y0, blockIdx.x, tid);
    __syncthreads();

    double csum = 0.0;                    // per-thread running loss

    for (int tile = blockIdx.x; tile < NTILES; tile += NCTA) {
        char* ycur = smem + (buf ? SM_Y1 : SM_Y0);
        char* ynxt = smem + (buf ? SM_Y0 : SM_Y1);

        // ---- HMMA mainloop
        float acc[2][8][4];
        #pragma unroll
        for (int rt = 0; rt < 2; rt++)
            #pragma unroll
            for (int t = 0; t < 8; t++) {
                acc[rt][t][0] = 0.f; acc[rt][t][1] = 0.f;
                acc[rt][t][2] = 0.f; acc[rt][t][3] = 0.f;
            }
        const uint32_t abase = smem_u32(ycur)
            + (uint32_t)((rb + (lane & 15))*YSTR + (lane >> 4)*8)*2;

        #pragma unroll
        for (int ks = 0; ks < 8; ks++) {
            uint4 bf[4];
            #pragma unroll
            for (int pp = 0; pp < 4; pp++) {
                uint32_t foff = (uint32_t)(((ks*8 + pb + pp)*32 + lane) * 16);
                bf[pp] = *(const uint4*)(smem + SM_DF + foff);
            }
            #pragma unroll
            for (int rt = 0; rt < 2; rt++) {
                uint32_t a0, a1, a2, a3;
                asm volatile("ldmatrix.sync.aligned.m8n8.x4.shared.b16 {%0,%1,%2,%3}, [%4];"
                             : "=r"(a0), "=r"(a1), "=r"(a2), "=r"(a3)
                             : "r"(abase + (uint32_t)(rt*16*YROWB) + ks*32));
                #pragma unroll
                for (int pp = 0; pp < 4; pp++) {
                    MMA_F16(acc[rt][2*pp+0], a0, a1, a2, a3, bf[pp].x, bf[pp].y);
                    MMA_F16(acc[rt][2*pp+1], a0, a1, a2, a3, bf[pp].z, bf[pp].w);
                }
            }
        }

        // ---- prefetch/convert next tile into the other buffer
        int ntile = tile + NCTA;
        if (ntile < NTILES) convert_tile(x, ynxt, ntile, tid);

        // ---- epilogue: d = y + P - x1, y/x1 fp16 from smem rows r / r+1
        float lsum = 0.f;
        #pragma unroll
        for (int rt = 0; rt < 2; rt++) {
            #pragma unroll
            for (int rr = 0; rr < 2; rr++) {
                int r  = rb + rt*16 + rr*8 + (lane >> 2);
                int rg = tile*TM + r;
                int b  = rg / 1023;
                int s  = rg - b*1023;
                const char* yrow  = ycur + (size_t)r*YROWB + (lane & 3)*4;
                const char* x1row = yrow + YROWB;
                bool bnd = (s == 1022);
                const float* gx1 = x + (size_t)(b*SS + s + 1)*H;
                #pragma unroll
                for (int t = 0; t < 8; t++) {
                    float2 yf = __half22float2(*(const __half2*)(yrow + (cb + t)*16));
                    float2 xf;
                    if (bnd) {
                        xf = *(const float2*)(gx1 + (cb + t)*8 + (lane & 3)*2);
                    } else {
                        xf = __half22float2(*(const __half2*)(x1row + (cb + t)*16));
                    }
                    float d;
                    d = yf.x + acc[rt][t][rr*2+0] - xf.x; lsum = fmaf(d, d, lsum);
                    d = yf.y + acc[rt][t][rr*2+1] - xf.y; lsum = fmaf(d, d, lsum);
                }
            }
        }
        csum += (double)lsum;

        __syncthreads();      // ycur reads done before next iter's convert
        buf ^= 1;
    }

    // ---- final CTA reduction of per-thread doubles (fixed order)
    #pragma unroll
    for (int off = 16; off; off >>= 1)
        csum += __shfl_down_sync(0xffffffffu, csum, off);
    __shared__ double redd[8];
    if (lane == 0) redd[w] = csum;
    __syncthreads();

    __shared__ bool is_last;
    if (tid == 0) {
        double s = 0.0;
        #pragma unroll
        for (int i = 0; i < 8; i++) s += redd[i];
        g_partials[blockIdx.x] = s;
        __threadfence();
        unsigned int old = atomicAdd(&g_done, 1u);
        is_last = (old == (unsigned int)(NCTA - 1));
    }
    __syncthreads();

    if (is_last) {
        double s = (tid < NCTA) ? g_partials[tid] : 0.0;
        if (tid + 256 < NCTA) s += g_partials[tid + 256];
        __shared__ double sd[256];
        sd[tid] = s; __syncthreads();
        for (int off = 128; off; off >>= 1) {
            if (tid < off) sd[tid] += sd[tid + off];
            __syncthreads();
        }
        if (tid == 0) {
            double step_loss = sd[0] / ((double)ROWS * (double)H);
            double l2_loss   = g_l2 / ((double)H * (double)H);
            out[0] = (float)(step_loss + 0.001 * l2_loss);
        }
    }
}

// ---------------------------------------------------------------- launch
extern "C" void kernel_launch(void* const* d_in, const int* in_sizes, int n_in,
                              void* d_out, int out_size) {
    const float* x     = (const float*)d_in[0];
    const float* coeff = (const float*)d_in[1];
    if (n_in >= 2 && in_sizes[0] == H*H) {
        coeff = (const float*)d_in[0];
        x     = (const float*)d_in[1];
    }
    float* out = (float*)d_out;

    cudaFuncSetAttribute(main_kernel,
                         cudaFuncAttributeMaxDynamicSharedMemorySize, SMEM_TOTAL);

    prep_kernel<<<H, 512>>>(coeff);
    main_kernel<<<NCTA, 256, SMEM_TOTAL>>>(x, out);
}

// round 13
// speedup vs baseline: 2.0089x; 1.0468x over previous
#include <cuda_runtime.h>
#include <cuda_fp16.h>
#include <cstdint>

// ---------------------------------------------------------------- constants
#define H 128
#define BB 256
#define SS 1024
#define ROWS (BB*(SS-1))          // 261888
#define TM 128                    // rows per tile
#define NTILES (ROWS/TM)          // 2046 (exact)
#define NCTA 296                  // persistent CTAs (2/SM x 148, all resident)

#define YSTR 136                  // fp16 elems per y-tile row (272 B, padded)
#define YROWB (YSTR*2)            // 272
#define YTILE (129*YROWB)         // 35088 (129 rows: +1 for x1 of row 127)

// dynamic smem layout (bytes)
#define SM_DF   0                         // D fp16 B-frags (paired), 32768
#define SM_Y0   32768
#define SM_Y1   (SM_Y0 + YTILE)
#define SMEM_TOTAL (SM_Y1 + YTILE)        // 102944 -> 2 CTAs/SM

// ---------------------------------------------------------------- scratch
__device__ float          g_B[H*H];          // C^2
__device__ __half         g_Dfrag[H*H];      // D fp16, paired B-frag order
__device__ double         g_partials[NCTA];
__device__ double         g_l2row[H];
__device__ double         g_l2;
__device__ unsigned int   g_done;
__device__ unsigned int   g_barA;            // prep phase barrier (128)
__device__ unsigned int   g_barB;            // all-CTA barrier (296)

// ---------------------------------------------------------------- helpers
__device__ __forceinline__ uint32_t smem_u32(const void* p) {
    uint32_t a;
    asm("{ .reg .u64 t; cvta.to.shared.u64 t, %1; cvt.u32.u64 %0, t; }"
        : "=r"(a) : "l"(p));
    return a;
}

#define MMA_F16(ACC, A0, A1, A2, A3, B0, B1)                                \
    asm volatile(                                                           \
        "mma.sync.aligned.m16n8k16.row.col.f32.f16.f16.f32 "                \
        "{%0,%1,%2,%3}, {%4,%5,%6,%7}, {%8,%9}, {%0,%1,%2,%3};"             \
        : "+f"((ACC)[0]), "+f"((ACC)[1]), "+f"((ACC)[2]), "+f"((ACC)[3])    \
        : "r"(A0), "r"(A1), "r"(A2), "r"(A3), "r"(B0), "r"(B1))

__device__ __forceinline__ void cvt_store16(char* dst, float4 v0, float4 v1) {
    __half2 p0 = __floats2half2_rn(v0.x, v0.y);
    __half2 p1 = __floats2half2_rn(v0.z, v0.w);
    __half2 p2 = __floats2half2_rn(v1.x, v1.y);
    __half2 p3 = __floats2half2_rn(v1.z, v1.w);
    uint4 u;
    u.x = *(uint32_t*)&p0; u.y = *(uint32_t*)&p1;
    u.z = *(uint32_t*)&p2; u.w = *(uint32_t*)&p3;
    *(uint4*)dst = u;
}

// ---------------------------------------------------------------- fused kernel
// 296 CTAs x 256 threads, 2 CTAs/SM (all co-resident -> global barriers OK).
// Stage 0: every CTA converts its first tile. Stage 1: CTAs 0..127 compute
// M = I + D (two phases, barrier-A). Stage 2: barrier-B, stage D, persistent
// mainloop with convert pipelined inside the mma loop. Final: fused reduction.
__global__ void __launch_bounds__(256, 2)
fused_kernel(const float* __restrict__ x, const float* __restrict__ coeff,
             float* __restrict__ out) {
    extern __shared__ char smem[];
    const int tid = threadIdx.x;
    const int cta = blockIdx.x;

    // ================= stage 0: convert first tile -> SM_Y0 (no D needed)
    {
        int row = tid >> 1, half = tid & 1;
        int rg = cta*TM + row;
        int b = rg / 1023, s = rg - b*1023;
        const float4* src = (const float4*)(x + (size_t)(b*SS + s)*H) + half*16;
        char* dst = smem + SM_Y0 + (size_t)row*YROWB + half*128;
        #pragma unroll
        for (int q = 0; q < 8; q++)
            cvt_store16(dst + q*16, src[2*q], src[2*q + 1]);
        if (tid < 32) {   // row 128 = x1 of row 127 (32 parallel LDGs)
            int rg7 = cta*TM + 127;
            int b7 = rg7 / 1023, s7 = rg7 - b7*1023;
            float4 v = *((const float4*)(x + (size_t)(b7*SS + s7 + 1)*H) + tid);
            __half2 p0 = __floats2half2_rn(v.x, v.y);
            __half2 p1 = __floats2half2_rn(v.z, v.w);
            uint2 u; u.x = *(uint32_t*)&p0; u.y = *(uint32_t*)&p1;
            *(uint2*)(smem + SM_Y0 + (size_t)128*YROWB + tid*8) = u;
        }
    }

    // ================= stage 1: prep (CTAs 0..127), smem overlaid on SM_Y1
    if (cta < H) {
        float* crow  = (float*)(smem + SM_Y1);
        float* brow  = crow + H;
        float* c2row = brow + H;
        float* part  = c2row + H;          // [2][H]
        const int i  = cta;
        const int j  = tid & 127;
        const int kh = tid >> 7;           // 0/1: k-half

        if (tid < H) crow[tid] = coeff[i*H + tid];
        __syncthreads();

        {   // phase 1: B[i][j] = sum_k crow[k] * C[k][j]
            float a0=0.f, a1=0.f, a2=0.f, a3=0.f;
            int k0 = kh * 64;
            #pragma unroll
            for (int k = 0; k < 64; k += 4) {
                a0 = fmaf(crow[k0+k],   __ldg(coeff + (k0+k)*H + j),   a0);
                a1 = fmaf(crow[k0+k+1], __ldg(coeff + (k0+k+1)*H + j), a1);
                a2 = fmaf(crow[k0+k+2], __ldg(coeff + (k0+k+2)*H + j), a2);
                a3 = fmaf(crow[k0+k+3], __ldg(coeff + (k0+k+3)*H + j), a3);
            }
            part[kh*H + j] = (a0+a1) + (a2+a3);
        }
        __syncthreads();
        if (tid < H) {
            float b = part[tid] + part[H + tid];
            g_B[i*H + tid] = b;
            brow[tid]  = b;
            c2row[tid] = crow[tid]*(1.0f/6.0f) + b*(1.0f/24.0f);
        }
        // per-row l2 partial (all 256 threads; >=128 contribute 0)
        {
            float v = 0.f;
            if (tid < H) { float c = crow[tid], cc = c*c; v = cc*cc; }
            #pragma unroll
            for (int off = 16; off; off >>= 1)
                v += __shfl_down_sync(0xffffffffu, v, off);
            __shared__ float lred[8];
            if ((tid & 31) == 0) lred[tid >> 5] = v;
            __syncthreads();
            if (tid == 0) {
                float s = 0.f;
                #pragma unroll
                for (int q = 0; q < 8; q++) s += lred[q];
                g_l2row[i] = (double)s;
            }
        }

        // barrier-A over the 128 prep CTAs
        __threadfence();
        __syncthreads();
        if (tid == 0) {
            atomicAdd(&g_barA, 1u);
            while (*(volatile unsigned int*)&g_barA < (unsigned int)H) { }
        }
        __syncthreads();
        __threadfence();

        {   // phase 2: D[i][j] = crow + B/2 + c2row @ B
            float a0=0.f, a1=0.f, a2=0.f, a3=0.f;
            int k0 = kh * 64;
            #pragma unroll
            for (int k = 0; k < 64; k += 4) {
                a0 = fmaf(c2row[k0+k],   __ldg(g_B + (k0+k)*H + j),   a0);
                a1 = fmaf(c2row[k0+k+1], __ldg(g_B + (k0+k+1)*H + j), a1);
                a2 = fmaf(c2row[k0+k+2], __ldg(g_B + (k0+k+2)*H + j), a2);
                a3 = fmaf(c2row[k0+k+3], __ldg(g_B + (k0+k+3)*H + j), a3);
            }
            part[kh*H + j] = (a0+a1) + (a2+a3);
        }
        __syncthreads();
        if (tid < H) {
            float d = crow[tid] + 0.5f*brow[tid] + (part[tid] + part[H + tid]);
            // paired m16n8k16 B-frag scatter (i = n, tid = k)
            int ks = tid >> 4, kin = tid & 15;
            int reg = kin >> 3;
            int lane = ((i & 7) << 2) + ((kin & 7) >> 1);
            int fidx = (((ks*8 + (i >> 4))*32 + lane) << 3)
                     + (((i >> 3) & 1) << 2) + (reg << 1) + (tid & 1);
            g_Dfrag[fidx] = __float2half_rn(d);
        }
        if (i == 0 && tid == 0) {
            double s = 0.0;
            #pragma unroll
            for (int r = 0; r < H; r++) s += g_l2row[r];
            g_l2 = s;
        }
    }

    // ================= stage 2: barrier-B over ALL 296 CTAs
    __threadfence();
    __syncthreads();
    if (tid == 0) {
        atomicAdd(&g_barB, 1u);
        while (*(volatile unsigned int*)&g_barB < (unsigned int)NCTA) { }
    }
    __syncthreads();
    __threadfence();

    // ---- stage D B-fragments once, 32KB
    {
        const uint4* df = (const uint4*)g_Dfrag;
        uint4* sh = (uint4*)(smem + SM_DF);
        #pragma unroll
        for (int q = 0; q < 8; q++) sh[tid + q*256] = df[tid + q*256];
    }
    __syncthreads();          // also publishes stage-0 tile0 converts

    // ================= persistent mainloop
    const int w    = tid >> 5;
    const int lane = tid & 31;
    const int rb   = (w & 3) * 32;
    const int cb   = (w >> 2) * 8;
    const int pb   = cb >> 1;
    const int vrow = tid >> 1, vhalf = tid & 1;    // convert mapping

    double csum = 0.0;
    int buf = 0;

    for (int tile = cta; tile < NTILES; tile += NCTA) {
        char* ycur = smem + (buf ? SM_Y1 : SM_Y0);
        char* ynxt = smem + (buf ? SM_Y0 : SM_Y1);

        const int ntile = tile + NCTA;
        const bool has_next = (ntile < NTILES);
        const float4* nsrc = (const float4*)x;
        char* ndst = ynxt + (size_t)vrow*YROWB + vhalf*128;
        if (has_next) {
            int rg = ntile*TM + vrow;
            int b = rg / 1023, s = rg - b*1023;
            nsrc = (const float4*)(x + (size_t)(b*SS + s)*H) + vhalf*16;
        }

        float acc[2][8][4];
        #pragma unroll
        for (int rt = 0; rt < 2; rt++)
            #pragma unroll
            for (int t = 0; t < 8; t++) {
                acc[rt][t][0] = 0.f; acc[rt][t][1] = 0.f;
                acc[rt][t][2] = 0.f; acc[rt][t][3] = 0.f;
            }
        const uint32_t abase = smem_u32(ycur)
            + (uint32_t)((rb + (lane & 15))*YSTR + (lane >> 4)*8)*2;

        // ---- mma loop with pipelined next-tile convert (1-chunk lookahead)
        float4 pf0, pf1;
        if (has_next) { pf0 = nsrc[0]; pf1 = nsrc[1]; }

        #pragma unroll
        for (int ks = 0; ks < 8; ks++) {
            float4 nf0, nf1;
            if (has_next && ks < 7) { nf0 = nsrc[2*ks+2]; nf1 = nsrc[2*ks+3]; }

            uint4 bf[4];
            #pragma unroll
            for (int pp = 0; pp < 4; pp++) {
                uint32_t foff = (uint32_t)(((ks*8 + pb + pp)*32 + lane) * 16);
                bf[pp] = *(const uint4*)(smem + SM_DF + foff);
            }
            #pragma unroll
            for (int rt = 0; rt < 2; rt++) {
                uint32_t a0, a1, a2, a3;
                asm volatile("ldmatrix.sync.aligned.m8n8.x4.shared.b16 {%0,%1,%2,%3}, [%4];"
                             : "=r"(a0), "=r"(a1), "=r"(a2), "=r"(a3)
                             : "r"(abase + (uint32_t)(rt*16*YROWB) + ks*32));
                #pragma unroll
                for (int pp = 0; pp < 4; pp++) {
                    MMA_F16(acc[rt][2*pp+0], a0, a1, a2, a3, bf[pp].x, bf[pp].y);
                    MMA_F16(acc[rt][2*pp+1], a0, a1, a2, a3, bf[pp].z, bf[pp].w);
                }
            }
            if (has_next) cvt_store16(ndst + ks*16, pf0, pf1);
            if (ks < 7) { pf0 = nf0; pf1 = nf1; }
        }

        // ---- row 128 of next tile (x1 of its row 127), 32 parallel LDGs
        if (has_next && tid < 32) {
            int rg7 = ntile*TM + 127;
            int b7 = rg7 / 1023, s7 = rg7 - b7*1023;
            float4 v = *((const float4*)(x + (size_t)(b7*SS + s7 + 1)*H) + tid);
            __half2 p0 = __floats2half2_rn(v.x, v.y);
            __half2 p1 = __floats2half2_rn(v.z, v.w);
            uint2 u; u.x = *(uint32_t*)&p0; u.y = *(uint32_t*)&p1;
            *(uint2*)(ynxt + (size_t)128*YROWB + tid*8) = u;
        }

        // ---- epilogue: d = y + P - x1, y/x1 fp16 from smem rows r / r+1
        float lsum = 0.f;
        #pragma unroll
        for (int rt = 0; rt < 2; rt++) {
            #pragma unroll
            for (int rr = 0; rr < 2; rr++) {
                int r  = rb + rt*16 + rr*8 + (lane >> 2);
                int rg = tile*TM + r;
                int b  = rg / 1023;
                int s  = rg - b*1023;
                const char* yrow  = ycur + (size_t)r*YROWB + (lane & 3)*4;
                const char* x1row = yrow + YROWB;
                bool bnd = (s == 1022);
                const float* gx1 = x + (size_t)(b*SS + s + 1)*H;
                #pragma unroll
                for (int t = 0; t < 8; t++) {
                    float2 yf = __half22float2(*(const __half2*)(yrow + (cb + t)*16));
                    float2 xf;
                    if (bnd) {
                        xf = *(const float2*)(gx1 + (cb + t)*8 + (lane & 3)*2);
                    } else {
                        xf = __half22float2(*(const __half2*)(x1row + (cb + t)*16));
                    }
                    float d;
                    d = yf.x + acc[rt][t][rr*2+0] - xf.x; lsum = fmaf(d, d, lsum);
                    d = yf.y + acc[rt][t][rr*2+1] - xf.y; lsum = fmaf(d, d, lsum);
                }
            }
        }
        csum += (double)lsum;

        __syncthreads();      // ycur reads + ynxt writes complete
        buf ^= 1;
    }

    // ================= final reduction (fixed order -> deterministic)
    #pragma unroll
    for (int off = 16; off; off >>= 1)
        csum += __shfl_down_sync(0xffffffffu, csum, off);
    __shared__ double redd[8];
    if (lane == 0) redd[w] = csum;
    __syncthreads();

    __shared__ bool is_last;
    if (tid == 0) {
        double s = 0.0;
        #pragma unroll
        for (int q = 0; q < 8; q++) s += redd[q];
        g_partials[cta] = s;
        __threadfence();
        unsigned int old = atomicAdd(&g_done, 1u);
        is_last = (old == (unsigned int)(NCTA - 1));
    }
    __syncthreads();

    if (is_last) {
        double s = (tid < NCTA) ? g_partials[tid] : 0.0;
        if (tid + 256 < NCTA) s += g_partials[tid + 256];
        __shared__ double sd[256];
        sd[tid] = s; __syncthreads();
        for (int off = 128; off; off >>= 1) {
            if (tid < off) sd[tid] += sd[tid + off];
            __syncthreads();
        }
        if (tid == 0) {
            double step_loss = sd[0] / ((double)ROWS * (double)H);
            double l2_loss   = g_l2 / ((double)H * (double)H);
            out[0] = (float)(step_loss + 0.001 * l2_loss);
            g_done = 0u; g_barA = 0u; g_barB = 0u;   // reset for graph replay
        }
    }
}

// ---------------------------------------------------------------- launch
extern "C" void kernel_launch(void* const* d_in, const int* in_sizes, int n_in,
                              void* d_out, int out_size) {
    const float* x     = (const float*)d_in[0];
    const float* coeff = (const float*)d_in[1];
    if (n_in >= 2 && in_sizes[0] == H*H) {
        coeff = (const float*)d_in[0];
        x     = (const float*)d_in[1];
    }
    float* out = (float*)d_out;

    cudaFuncSetAttribute(fused_kernel,
                         cudaFuncAttributeMaxDynamicSharedMemorySize, SMEM_TOTAL);

    fused_kernel<<<NCTA, 256, SMEM_TOTAL>>>(x, coeff, out);
}